// round 7
// baseline (speedup 1.0000x reference)
#include <cuda_runtime.h>

// ---------------------------------------------------------------------------
// MSRNN: 3-layer GRU-variant.
//   E_l[t] = xs[t] @ Wxh_l^T + ms_l[t] @ Wnh_l^T + bxh_l + bnh_l   (precompute)
//   step:  gh = h @ Whh^T + bhh
//          r = sig(E_r + gh_r); i = sig(E_i + gh_i); n = tanh(E_n + r*gh_n)
//          h' = n + i*(h - n)
// Persistent kernel per layer + CG-style grid barrier.
// Layer kernel v3: lane tile 4 batches x 6 gate-rows, K split 8-way within
// warp (shuffle reduction). Crossbar bytes cut 3.2x vs v1.
// ---------------------------------------------------------------------------

#define T0 512
#define T1 511
#define T2 509
#define BB 32
#define HID 1024
#define G3 3072
#define DIN 256

#define M0 (T0*BB)
#define M1 (T1*BB)
#define M2 (T2*BB)

#define OFF1 (T0*BB*DIN)
#define OFF2 (OFF1 + T1*BB*DIN)
#define OFFH (OFF2 + T2*BB*DIN)

#define NBLK 128
#define WPAD 1028          // W row stride (floats) = 257 vec4 (≡1 mod 8)
#define HPAD 516           // h row stride (floats) = 129 vec4 (≡1 mod 8)
#define KCH  512

// ------------------------- scratch (device globals) ------------------------
__device__ float g_x  [(size_t)T0*BB*DIN];
__device__ float g_ms1[(size_t)T1*BB*DIN];
__device__ float g_ms2[(size_t)T2*BB*DIN];
__device__ float g_E0 [(size_t)T0*BB*G3];
__device__ float g_E1 [(size_t)T1*BB*G3];
__device__ float g_E2 [(size_t)T2*BB*G3];
__device__ float g_Y0 [(size_t)T0*BB*HID];
__device__ float g_Y1 [(size_t)T1*BB*HID];
__device__ float g_Y2 [(size_t)T2*BB*HID];
__device__ float g_bs [3*G3];

__device__ unsigned int g_cnt = 0;
__device__ volatile unsigned int g_gen = 0;

// ------------------------- packed f32x2 helpers -----------------------------
__device__ __forceinline__ unsigned long long pk2(float lo, float hi) {
    unsigned long long r;
    asm("mov.b64 %0, {%1, %2};" : "=l"(r) : "f"(lo), "f"(hi));
    return r;
}
__device__ __forceinline__ void fma2(unsigned long long& d,
                                     unsigned long long a,
                                     unsigned long long b) {
    asm("fma.rn.f32x2 %0, %1, %2, %0;" : "+l"(d) : "l"(a), "l"(b));
}
__device__ __forceinline__ float2 up2(unsigned long long v) {
    float2 f;
    asm("mov.b64 {%0, %1}, %2;" : "=f"(f.x), "=f"(f.y) : "l"(v));
    return f;
}
__device__ __forceinline__ float hadd2(unsigned long long v) {
    float2 f = up2(v);
    return f.x + f.y;
}
union U4 {
    float4 f4;
    struct { unsigned long long a, b; } s;
};

// ------------------------- prep: transpose + moving means -------------------
__global__ void prep_kernel(const float* __restrict__ in) {
    int i = blockIdx.x * blockDim.x + threadIdx.x;
    if (i >= T0 * BB * DIN) return;
    int d = i % DIN;
    int tb = i / DIN;
    int b = tb % BB;
    int t = tb / BB;
    const float v0 = in[((size_t)b * T0 + t) * DIN + d];
    g_x[i] = v0;
    if (t < T1) {
        float v1 = in[((size_t)b * T0 + t + 1) * DIN + d];
        g_ms1[((size_t)t * BB + b) * DIN + d] = 0.5f * (v0 + v1);
        if (t < T2) {
            float v2 = in[((size_t)b * T0 + t + 2) * DIN + d];
            float v3 = in[((size_t)b * T0 + t + 3) * DIN + d];
            g_ms2[((size_t)t * BB + b) * DIN + d] = 0.25f * (v0 + v1 + v2 + v3);
        }
    }
}

__global__ void bias_sum_kernel(const float* __restrict__ b0x, const float* __restrict__ b0n,
                                const float* __restrict__ b1x, const float* __restrict__ b1n,
                                const float* __restrict__ b2x, const float* __restrict__ b2n) {
    int i = blockIdx.x * blockDim.x + threadIdx.x;
    if (i >= G3) return;
    g_bs[i]          = b0x[i] + b0n[i];
    g_bs[G3 + i]     = b1x[i] + b1n[i];
    g_bs[2 * G3 + i] = b2x[i] + b2n[i];
}

// ------------------------- GEMM (round-2 proven config) ---------------------
#define GBM 128
#define GBN 64
#define GBK 16

__global__ __launch_bounds__(256) void gemm_nt(
    float* __restrict__ C, const float* __restrict__ A, const float* __restrict__ W,
    const float* __restrict__ bias, int M, int N, int K, int accum)
{
    __shared__ float As[GBK][GBM + 4];
    __shared__ float Bs[GBK][GBN + 4];

    int tid = threadIdx.x;
    int n0 = blockIdx.x * GBN;
    int m0 = blockIdx.y * GBM;
    int ty = tid >> 4, tx = tid & 15;
    int mb = ty * 8, nb = tx * 4;

    unsigned long long acc[4][4];
#pragma unroll
    for (int i = 0; i < 4; i++)
#pragma unroll
        for (int j = 0; j < 4; j++) acc[i][j] = 0ull;

    int arow = tid >> 2;
    int ac4  = (tid & 3) * 4;

    for (int k0 = 0; k0 < K; k0 += GBK) {
#pragma unroll
        for (int r = 0; r < 2; r++) {
            int m = arow + r * 64;
            int gm = m0 + m;
            if (gm > M - 1) gm = M - 1;
            float4 v = *(const float4*)&A[(size_t)gm * K + k0 + ac4];
            As[ac4 + 0][m] = v.x; As[ac4 + 1][m] = v.y;
            As[ac4 + 2][m] = v.z; As[ac4 + 3][m] = v.w;
        }
        {
            int n = arow;
            float4 v = *(const float4*)&W[(size_t)(n0 + n) * K + k0 + ac4];
            Bs[ac4 + 0][n] = v.x; Bs[ac4 + 1][n] = v.y;
            Bs[ac4 + 2][n] = v.z; Bs[ac4 + 3][n] = v.w;
        }
        __syncthreads();
#pragma unroll
        for (int kk = 0; kk < GBK; kk++) {
            U4 a0; a0.f4 = *(const float4*)&As[kk][mb];
            U4 a1; a1.f4 = *(const float4*)&As[kk][mb + 4];
            float4 bv = *(const float4*)&Bs[kk][nb];
            unsigned long long b0 = pk2(bv.x, bv.x), b1 = pk2(bv.y, bv.y);
            unsigned long long b2 = pk2(bv.z, bv.z), b3 = pk2(bv.w, bv.w);
            fma2(acc[0][0], a0.s.a, b0); fma2(acc[0][1], a0.s.a, b1);
            fma2(acc[0][2], a0.s.a, b2); fma2(acc[0][3], a0.s.a, b3);
            fma2(acc[1][0], a0.s.b, b0); fma2(acc[1][1], a0.s.b, b1);
            fma2(acc[1][2], a0.s.b, b2); fma2(acc[1][3], a0.s.b, b3);
            fma2(acc[2][0], a1.s.a, b0); fma2(acc[2][1], a1.s.a, b1);
            fma2(acc[2][2], a1.s.a, b2); fma2(acc[2][3], a1.s.a, b3);
            fma2(acc[3][0], a1.s.b, b0); fma2(acc[3][1], a1.s.b, b1);
            fma2(acc[3][2], a1.s.b, b2); fma2(acc[3][3], a1.s.b, b3);
        }
        __syncthreads();
    }

#pragma unroll
    for (int mp = 0; mp < 4; mp++) {
#pragma unroll
        for (int n = 0; n < 4; n++) {
            float2 v = up2(acc[mp][n]);
            int col = n0 + nb + n;
            int r0 = m0 + mb + 2 * mp;
            float badd = bias ? bias[col] : 0.f;
            if (r0 < M) {
                size_t idx = (size_t)r0 * N + col;
                C[idx] = v.x + (accum ? C[idx] : badd);
            }
            if (r0 + 1 < M) {
                size_t idx = (size_t)(r0 + 1) * N + col;
                C[idx] = v.y + (accum ? C[idx] : badd);
            }
        }
    }
}

// ------------------------- persistent recurrent layer -----------------------
__device__ __forceinline__ void grid_barrier() {
    __syncthreads();
    if (threadIdx.x == 0) {
        __threadfence();
        unsigned int g = g_gen;
        if (atomicAdd(&g_cnt, 1u) == NBLK - 1) {
            g_cnt = 0;
            __threadfence();
            g_gen = g + 1;
        } else {
            while (g_gen == g) { __nanosleep(64); }
            __threadfence();
        }
    }
    __syncthreads();
}

// 128 blocks x 256 threads. Block owns 8 hidden units (24 Whh gate rows in
// SMEM). warp w: ug = w>>1 (unit pair: units 2ug,2ug+1), bgh = w&1.
// lane: ks = lane>>2 (k-slice 0..7), bgl = lane&3; bg = bgh*4+bgl.
// Lane tile: batches bg*4..bg*4+3, rows (g, ug*2+uu) for g=0..2, uu=0..1.
__global__ __launch_bounds__(256, 1) void layer_kernel(
    float* __restrict__ Y, const float* __restrict__ E,
    const float* __restrict__ Whh, const float* __restrict__ bhh, int T)
{
    extern __shared__ float smem[];
    float* Wsh = smem;                   // [24][WPAD]
    float* hs  = Wsh + 24 * WPAD;        // [32][HPAD]
    float* Esh = hs + 32 * HPAD;         // [24][33]

    const int tid  = threadIdx.x;
    const int lane = tid & 31;
    const int w    = tid >> 5;
    const int ks   = lane >> 2;
    const int bgl  = lane & 3;
    const int ug   = w >> 1;
    const int bgh  = w & 1;
    const int bg   = bgh * 4 + bgl;
    const int blk  = blockIdx.x;

    // --- load Whh slice: Wsh row r = g*8+uu <- Whh row g*1024 + blk*8 + uu ---
#pragma unroll
    for (int i = 0; i < 24; i++) {
        int idx = tid + i * 256;
        int r   = idx >> 8;
        int c4  = (idx & 255) * 4;
        int gg  = r >> 3, uu = r & 7;
        float4 v = *(const float4*)&Whh[(size_t)(gg * HID + blk * 8 + uu) * HID + c4];
        *(float4*)&Wsh[r * WPAD + c4] = v;
    }

    // epilogue biases per lane: r6 = g*2+uu -> bhh[g*HID + blk*8 + ug*2+uu]
    float eb[6];
#pragma unroll
    for (int r6 = 0; r6 < 6; r6++) {
        int g = r6 >> 1, uu = r6 & 1;
        eb[r6] = bhh[g * HID + blk * 8 + ug * 2 + uu];
    }

    __syncthreads();

    // ---- t = 0 (h = 0): 256 threads = 256 cells ----
    {
        int b0 = tid & 31, jj0 = tid >> 5;
        int j0 = blk * 8 + jj0;
        const float* Et = E + (size_t)b0 * G3;
        float er = Et[j0], ei = Et[HID + j0], en = Et[2 * HID + j0];
        float brr = bhh[j0], bii = bhh[HID + j0], bnn = bhh[2 * HID + j0];
        float r  = 1.f / (1.f + __expf(-(er + brr)));
        float ig = 1.f / (1.f + __expf(-(ei + bii)));
        float n  = tanhf(en + r * bnn);
        Y[(size_t)b0 * HID + j0] = n - ig * n;
        grid_barrier();
    }

    const bool epi = (ks == 0);

    for (int t = 1; t < T; t++) {
        const float* hprev = Y + (size_t)(t - 1) * BB * HID;

        // E prefetch (3 scalars/thread, published to Esh under chunk-1 sync)
        float ept[3];
#pragma unroll
        for (int q = 0; q < 3; q++) {
            int idx = tid + q * 256;
            int b = idx & 31, r24 = idx >> 5;
            int g = r24 >> 3, jj = r24 & 7;
            ept[q] = __ldcg(&E[((size_t)t * BB + b) * G3 + g * HID + blk * 8 + jj]);
        }
        // hp prefetch for epilogue lanes (8 cells: 2 uu x 4 batches)
        float hp[8];
        if (epi) {
#pragma unroll
            for (int uu = 0; uu < 2; uu++)
#pragma unroll
                for (int i = 0; i < 4; i++)
                    hp[uu * 4 + i] =
                        __ldcg(&hprev[(size_t)(bg * 4 + i) * HID + blk * 8 + ug * 2 + uu]);
        }

        unsigned long long acc[24];   // acc[r6*4 + i]
#pragma unroll
        for (int i = 0; i < 24; i++) acc[i] = 0ull;

#pragma unroll
        for (int c = 0; c < 2; c++) {
            // stage h chunk c (32 rows x 512 floats)
#pragma unroll
            for (int i2 = 0; i2 < 16; i2++) {
                int idx = tid + i2 * 256;
                int hb  = idx >> 7;
                int k4  = (idx & 127) * 4;
                float4 v = __ldcg((const float4*)&hprev[(size_t)hb * HID + c * KCH + k4]);
                *(float4*)&hs[hb * HPAD + k4] = v;
            }
            if (c == 1) {
#pragma unroll
                for (int q = 0; q < 3; q++) {
                    int idx = tid + q * 256;
                    Esh[(idx >> 5) * 33 + (idx & 31)] = ept[q];
                }
            }
            __syncthreads();

#pragma unroll 4
            for (int m = 0; m < 16; m++) {
                int k4  = (ks + 8 * m) * 4;       // float offset in staged chunk
                int k4w = c * KCH + k4;           // absolute k for W
                U4 hv[4];
#pragma unroll
                for (int i = 0; i < 4; i++)
                    hv[i].f4 = *(const float4*)&hs[(bg * 4 + i) * HPAD + k4];
#pragma unroll
                for (int r6 = 0; r6 < 6; r6++) {
                    int g = r6 >> 1, uu = r6 & 1;
                    U4 wv; wv.f4 = *(const float4*)&Wsh[(g * 8 + ug * 2 + uu) * WPAD + k4w];
#pragma unroll
                    for (int i = 0; i < 4; i++) {
                        fma2(acc[r6 * 4 + i], hv[i].s.a, wv.s.a);
                        fma2(acc[r6 * 4 + i], hv[i].s.b, wv.s.b);
                    }
                }
            }
            __syncthreads();
        }

        // reduce over ks (lanes differing in bits 2..4): 3 butterfly rounds
        float s[24];
#pragma unroll
        for (int i = 0; i < 24; i++) s[i] = hadd2(acc[i]);
#pragma unroll
        for (int d = 4; d <= 16; d <<= 1)
#pragma unroll
            for (int i = 0; i < 24; i++)
                s[i] += __shfl_xor_sync(0xffffffffu, s[i], d);

        if (epi) {
            // epilogue: 8 GRU cells per epilogue lane
#pragma unroll
            for (int uu = 0; uu < 2; uu++) {
                int jj = ug * 2 + uu;
#pragma unroll
                for (int i = 0; i < 4; i++) {
                    int b = bg * 4 + i;
                    float gr = s[(0 + uu) * 4 + i] + eb[0 + uu];
                    float gi = s[(2 + uu) * 4 + i] + eb[2 + uu];
                    float gn = s[(4 + uu) * 4 + i] + eb[4 + uu];
                    float er = Esh[(0 * 8 + jj) * 33 + b];
                    float ei = Esh[(1 * 8 + jj) * 33 + b];
                    float en = Esh[(2 * 8 + jj) * 33 + b];
                    float r  = 1.f / (1.f + __expf(-(er + gr)));
                    float ig = 1.f / (1.f + __expf(-(ei + gi)));
                    float n  = tanhf(en + r * gn);
                    Y[(size_t)t * BB * HID + (size_t)b * HID + blk * 8 + jj] =
                        n + ig * (hp[uu * 4 + i] - n);
                }
            }
        }

        if (t != T - 1) grid_barrier();
    }
}

// ------------------------- final hidden-state copy --------------------------
__global__ void copy_hidden(float* __restrict__ out) {
    int i = blockIdx.x * blockDim.x + threadIdx.x;
    if (i >= 3 * BB * HID) return;
    int l = i / (BB * HID);
    int r = i % (BB * HID);
    const float* src;
    if (l == 0)      src = g_Y0 + (size_t)(T0 - 1) * BB * HID;
    else if (l == 1) src = g_Y1 + (size_t)(T1 - 1) * BB * HID;
    else             src = g_Y2 + (size_t)(T2 - 1) * BB * HID;
    out[i] = src[r];
}

// ---------------------------------------------------------------------------
extern "C" void kernel_launch(void* const* d_in, const int* in_sizes, int n_in,
                              void* d_out, int out_size)
{
    const float* inputs = (const float*)d_in[0];
    const float* Wxh0 = (const float*)d_in[1];
    const float* bxh0 = (const float*)d_in[2];
    const float* Whh0 = (const float*)d_in[3];
    const float* bhh0 = (const float*)d_in[4];
    const float* Wnh0 = (const float*)d_in[5];
    const float* bnh0 = (const float*)d_in[6];
    const float* Wxh1 = (const float*)d_in[7];
    const float* bxh1 = (const float*)d_in[8];
    const float* Whh1 = (const float*)d_in[9];
    const float* bhh1 = (const float*)d_in[10];
    const float* Wnh1 = (const float*)d_in[11];
    const float* bnh1 = (const float*)d_in[12];
    const float* Wxh2 = (const float*)d_in[13];
    const float* bxh2 = (const float*)d_in[14];
    const float* Whh2 = (const float*)d_in[15];
    const float* bhh2 = (const float*)d_in[16];
    const float* Wnh2 = (const float*)d_in[17];
    const float* bnh2 = (const float*)d_in[18];
    const float* Wout = (const float*)d_in[19];
    const float* bout = (const float*)d_in[20];

    float *pX, *pM1, *pM2, *pE0, *pE1, *pE2, *pY0, *pY1, *pY2, *pBS;
    cudaGetSymbolAddress((void**)&pX,  g_x);
    cudaGetSymbolAddress((void**)&pM1, g_ms1);
    cudaGetSymbolAddress((void**)&pM2, g_ms2);
    cudaGetSymbolAddress((void**)&pE0, g_E0);
    cudaGetSymbolAddress((void**)&pE1, g_E1);
    cudaGetSymbolAddress((void**)&pE2, g_E2);
    cudaGetSymbolAddress((void**)&pY0, g_Y0);
    cudaGetSymbolAddress((void**)&pY1, g_Y1);
    cudaGetSymbolAddress((void**)&pY2, g_Y2);
    cudaGetSymbolAddress((void**)&pBS, g_bs);

    static int smem_set = 0;
    const int LSMEM = (24 * WPAD + 32 * HPAD + 24 * 33) * 4;   // 167,904 B
    if (!smem_set) {
        cudaFuncSetAttribute(layer_kernel,
                             cudaFuncAttributeMaxDynamicSharedMemorySize, LSMEM);
        smem_set = 1;
    }

    float* out = (float*)d_out;

    prep_kernel<<<(T0 * BB * DIN + 255) / 256, 256>>>(inputs);
    bias_sum_kernel<<<(G3 + 255) / 256, 256>>>(bxh0, bnh0, bxh1, bnh1, bxh2, bnh2);

    // ---- layer 0 E ----
    gemm_nt<<<dim3(G3 / GBN, (M0 + GBM - 1) / GBM), 256>>>(pE0, pX, Wxh0, pBS, M0, G3, DIN, 0);
    gemm_nt<<<dim3(G3 / GBN, (M0 + GBM - 1) / GBM), 256>>>(pE0, pX, Wnh0, 0,   M0, G3, DIN, 1);
    // ---- layer 1 ms-part (independent of Y0) ----
    gemm_nt<<<dim3(G3 / GBN, (M1 + GBM - 1) / GBM), 256>>>(pE1, pM1, Wnh1, pBS + G3, M1, G3, DIN, 0);

    layer_kernel<<<NBLK, 256, LSMEM>>>(pY0, pE0, Whh0, bhh0, T0);

    // ---- layer 1 xs-part (Y0 shifted by 1 step), accumulate ----
    gemm_nt<<<dim3(G3 / GBN, (M1 + GBM - 1) / GBM), 256>>>(pE1, pY0 + BB * HID, Wxh1, 0, M1, G3, HID, 1);
    layer_kernel<<<NBLK, 256, LSMEM>>>(pY1, pE1, Whh1, bhh1, T1);

    // ---- layer 2 ----
    gemm_nt<<<dim3(G3 / GBN, (M2 + GBM - 1) / GBM), 256>>>(pE2, pM2, Wnh2, pBS + 2 * G3, M2, G3, DIN, 0);
    gemm_nt<<<dim3(G3 / GBN, (M2 + GBM - 1) / GBM), 256>>>(pE2, pY1 + 2 * BB * HID, Wxh2, 0, M2, G3, HID, 1);
    layer_kernel<<<NBLK, 256, LSMEM>>>(pY2, pE2, Whh2, bhh2, T2);

    // ---- output projections + hidden states ----
    gemm_nt<<<dim3(DIN / GBN, (M0 + GBM - 1) / GBM), 256>>>(out,        pY0, Wout, bout, M0, DIN, HID, 0);
    gemm_nt<<<dim3(DIN / GBN, (M1 + GBM - 1) / GBM), 256>>>(out + OFF1, pY1, Wout, bout, M1, DIN, HID, 0);
    gemm_nt<<<dim3(DIN / GBN, (M2 + GBM - 1) / GBM), 256>>>(out + OFF2, pY2, Wout, bout, M2, DIN, HID, 0);
    copy_hidden<<<(3 * BB * HID + 255) / 256, 256>>>(out + OFFH);
}

// round 8
// speedup vs baseline: 1.4298x; 1.4298x over previous
#include <cuda_runtime.h>

// ---------------------------------------------------------------------------
// MSRNN: 3-layer GRU-variant.
//   E_l[t] = xs[t] @ Wxh_l^T + ms_l[t] @ Wnh_l^T + bxh_l + bnh_l   (precompute)
//   step:  gh = h @ Whh^T + bhh
//          r = sig(E_r + gh_r); i = sig(E_i + gh_i); n = tanh(E_n + r*gh_n)
//          h' = n + i*(h - n)
// Persistent kernel per layer + CG-style grid barrier (r6 proven).
// Round 8: E0 fused (ms0 == x  =>  one GEMM with Wxh0+Wnh0), and the layer
// kernel uses double-buffered h staging (one less sync, LDG hidden).
// ---------------------------------------------------------------------------

#define T0 512
#define T1 511
#define T2 509
#define BB 32
#define HID 1024
#define G3 3072
#define DIN 256

#define M0 (T0*BB)
#define M1 (T1*BB)
#define M2 (T2*BB)

#define OFF1 (T0*BB*DIN)
#define OFF2 (OFF1 + T1*BB*DIN)
#define OFFH (OFF2 + T2*BB*DIN)

#define NBLK 128
#define WPAD 1028
#define HPAD 516
#define KCH  512

// ------------------------- scratch (device globals) ------------------------
__device__ float g_x   [(size_t)T0*BB*DIN];
__device__ float g_ms1 [(size_t)T1*BB*DIN];
__device__ float g_ms2 [(size_t)T2*BB*DIN];
__device__ float g_E0  [(size_t)T0*BB*G3];
__device__ float g_E1  [(size_t)T1*BB*G3];
__device__ float g_E2  [(size_t)T2*BB*G3];
__device__ float g_Y0  [(size_t)T0*BB*HID];
__device__ float g_Y1  [(size_t)T1*BB*HID];
__device__ float g_Y2  [(size_t)T2*BB*HID];
__device__ float g_bs  [3*G3];
__device__ float g_Wsum[(size_t)G3*DIN];

__device__ unsigned int g_cnt = 0;
__device__ volatile unsigned int g_gen = 0;

// ------------------------- packed f32x2 helpers -----------------------------
__device__ __forceinline__ unsigned long long pk2(float lo, float hi) {
    unsigned long long r;
    asm("mov.b64 %0, {%1, %2};" : "=l"(r) : "f"(lo), "f"(hi));
    return r;
}
__device__ __forceinline__ void fma2(unsigned long long& d,
                                     unsigned long long a,
                                     unsigned long long b) {
    asm("fma.rn.f32x2 %0, %1, %2, %0;" : "+l"(d) : "l"(a), "l"(b));
}
__device__ __forceinline__ float2 up2(unsigned long long v) {
    float2 f;
    asm("mov.b64 {%0, %1}, %2;" : "=f"(f.x), "=f"(f.y) : "l"(v));
    return f;
}
__device__ __forceinline__ float hadd2(unsigned long long v) {
    float2 f = up2(v);
    return f.x + f.y;
}
union U4 {
    float4 f4;
    struct { unsigned long long a, b; } s;
};

// ------------------------- prep: transpose + moving means -------------------
__global__ void prep_kernel(const float* __restrict__ in) {
    int i = blockIdx.x * blockDim.x + threadIdx.x;
    if (i >= T0 * BB * DIN) return;
    int d = i % DIN;
    int tb = i / DIN;
    int b = tb % BB;
    int t = tb / BB;
    const float v0 = in[((size_t)b * T0 + t) * DIN + d];
    g_x[i] = v0;
    if (t < T1) {
        float v1 = in[((size_t)b * T0 + t + 1) * DIN + d];
        g_ms1[((size_t)t * BB + b) * DIN + d] = 0.5f * (v0 + v1);
        if (t < T2) {
            float v2 = in[((size_t)b * T0 + t + 2) * DIN + d];
            float v3 = in[((size_t)b * T0 + t + 3) * DIN + d];
            g_ms2[((size_t)t * BB + b) * DIN + d] = 0.25f * (v0 + v1 + v2 + v3);
        }
    }
}

// combined biases + Wsum0 = Wxh0 + Wnh0 (layer-0 fusion)
__global__ void bias_wsum_kernel(const float* __restrict__ b0x, const float* __restrict__ b0n,
                                 const float* __restrict__ b1x, const float* __restrict__ b1n,
                                 const float* __restrict__ b2x, const float* __restrict__ b2n,
                                 const float* __restrict__ Wxh0, const float* __restrict__ Wnh0) {
    int i = blockIdx.x * blockDim.x + threadIdx.x;
    if (i < G3) {
        g_bs[i]          = b0x[i] + b0n[i];
        g_bs[G3 + i]     = b1x[i] + b1n[i];
        g_bs[2 * G3 + i] = b2x[i] + b2n[i];
    }
    if (i < G3 * DIN) g_Wsum[i] = Wxh0[i] + Wnh0[i];
}

// ------------------------- GEMM (round-2 proven config) ---------------------
#define GBM 128
#define GBN 64
#define GBK 16

__global__ __launch_bounds__(256) void gemm_nt(
    float* __restrict__ C, const float* __restrict__ A, const float* __restrict__ W,
    const float* __restrict__ bias, int M, int N, int K, int accum)
{
    __shared__ float As[GBK][GBM + 4];
    __shared__ float Bs[GBK][GBN + 4];

    int tid = threadIdx.x;
    int n0 = blockIdx.x * GBN;
    int m0 = blockIdx.y * GBM;
    int ty = tid >> 4, tx = tid & 15;
    int mb = ty * 8, nb = tx * 4;

    unsigned long long acc[4][4];
#pragma unroll
    for (int i = 0; i < 4; i++)
#pragma unroll
        for (int j = 0; j < 4; j++) acc[i][j] = 0ull;

    int arow = tid >> 2;
    int ac4  = (tid & 3) * 4;

    for (int k0 = 0; k0 < K; k0 += GBK) {
#pragma unroll
        for (int r = 0; r < 2; r++) {
            int m = arow + r * 64;
            int gm = m0 + m;
            if (gm > M - 1) gm = M - 1;
            float4 v = *(const float4*)&A[(size_t)gm * K + k0 + ac4];
            As[ac4 + 0][m] = v.x; As[ac4 + 1][m] = v.y;
            As[ac4 + 2][m] = v.z; As[ac4 + 3][m] = v.w;
        }
        {
            int n = arow;
            float4 v = *(const float4*)&W[(size_t)(n0 + n) * K + k0 + ac4];
            Bs[ac4 + 0][n] = v.x; Bs[ac4 + 1][n] = v.y;
            Bs[ac4 + 2][n] = v.z; Bs[ac4 + 3][n] = v.w;
        }
        __syncthreads();
#pragma unroll
        for (int kk = 0; kk < GBK; kk++) {
            U4 a0; a0.f4 = *(const float4*)&As[kk][mb];
            U4 a1; a1.f4 = *(const float4*)&As[kk][mb + 4];
            float4 bv = *(const float4*)&Bs[kk][nb];
            unsigned long long b0 = pk2(bv.x, bv.x), b1 = pk2(bv.y, bv.y);
            unsigned long long b2 = pk2(bv.z, bv.z), b3 = pk2(bv.w, bv.w);
            fma2(acc[0][0], a0.s.a, b0); fma2(acc[0][1], a0.s.a, b1);
            fma2(acc[0][2], a0.s.a, b2); fma2(acc[0][3], a0.s.a, b3);
            fma2(acc[1][0], a0.s.b, b0); fma2(acc[1][1], a0.s.b, b1);
            fma2(acc[1][2], a0.s.b, b2); fma2(acc[1][3], a0.s.b, b3);
            fma2(acc[2][0], a1.s.a, b0); fma2(acc[2][1], a1.s.a, b1);
            fma2(acc[2][2], a1.s.a, b2); fma2(acc[2][3], a1.s.a, b3);
            fma2(acc[3][0], a1.s.b, b0); fma2(acc[3][1], a1.s.b, b1);
            fma2(acc[3][2], a1.s.b, b2); fma2(acc[3][3], a1.s.b, b3);
        }
        __syncthreads();
    }

#pragma unroll
    for (int mp = 0; mp < 4; mp++) {
#pragma unroll
        for (int n = 0; n < 4; n++) {
            float2 v = up2(acc[mp][n]);
            int col = n0 + nb + n;
            int r0 = m0 + mb + 2 * mp;
            float badd = bias ? bias[col] : 0.f;
            if (r0 < M) {
                size_t idx = (size_t)r0 * N + col;
                C[idx] = v.x + (accum ? C[idx] : badd);
            }
            if (r0 + 1 < M) {
                size_t idx = (size_t)(r0 + 1) * N + col;
                C[idx] = v.y + (accum ? C[idx] : badd);
            }
        }
    }
}

// ------------------------- persistent recurrent layer -----------------------
__device__ __forceinline__ void grid_barrier() {
    __syncthreads();
    if (threadIdx.x == 0) {
        __threadfence();
        unsigned int g = g_gen;
        if (atomicAdd(&g_cnt, 1u) == NBLK - 1) {
            g_cnt = 0;
            __threadfence();
            g_gen = g + 1;
        } else {
            while (g_gen == g) { __nanosleep(64); }
            __threadfence();
        }
    }
    __syncthreads();
}

// 128 blocks x 256 threads. Block owns 8 hidden units (24 Whh gate-rows in
// SMEM for the whole layer). warp w = batches 4w..4w+3; u = lane>>2.
// Double-buffered h staging: chunk0 -> hs0, chunk1 -> hs1 (STS after
// chunk-0 compute; only two __syncthreads per step).
__global__ __launch_bounds__(256, 1) void layer_kernel(
    float* __restrict__ Y, const float* __restrict__ E,
    const float* __restrict__ Whh, const float* __restrict__ bhh, int T)
{
    extern __shared__ float smem[];
    float* Wsh = smem;                      // [24][WPAD]
    float* hs0 = Wsh + 24 * WPAD;           // [32][HPAD]
    float* hs1 = hs0 + 32 * HPAD;           // [32][HPAD]

    int tid  = threadIdx.x;
    int lane = tid & 31;
    int w    = tid >> 5;
    int u    = lane >> 2;
    int b    = 4 * w + (lane & 3);
    int j    = blockIdx.x * 8 + u;

    // --- load Whh slice: rows g*1024 + (blk*8+u) -> Wsh[g*8+u][*] ---
#pragma unroll
    for (int i = 0; i < 24; i++) {
        int idx = tid + i * 256;
        int r   = idx >> 8;
        int c4  = (idx & 255) * 4;
        int gg  = r >> 3, uu = r & 7;
        float4 v = *(const float4*)&Whh[(size_t)(gg * HID + blockIdx.x * 8 + uu) * HID + c4];
        *(float4*)&Wsh[(size_t)r * WPAD + c4] = v;
    }

    const float* Wr = Wsh + (size_t)(0 * 8 + u) * WPAD;
    const float* Wi = Wsh + (size_t)(1 * 8 + u) * WPAD;
    const float* Wn = Wsh + (size_t)(2 * 8 + u) * WPAD;
    const float* hrow0 = hs0 + (size_t)b * HPAD;
    const float* hrow1 = hs1 + (size_t)b * HPAD;

    float br = bhh[j];
    float bi = bhh[HID + j];
    float bn = bhh[2 * HID + j];

    __syncthreads();

    // ---- t = 0: h = 0 ----
    {
        const float* Et = E + (size_t)b * G3;
        float er = Et[j];
        float ei = Et[HID + j];
        float en = Et[2 * HID + j];
        float r  = 1.f / (1.f + __expf(-(er + br)));
        float ig = 1.f / (1.f + __expf(-(ei + bi)));
        float n  = tanhf(en + r * bn);
        Y[(size_t)b * HID + j] = n - ig * n;
        grid_barrier();
    }

    for (int t = 1; t < T; t++) {
        const float* hprev = Y + (size_t)(t - 1) * BB * HID;

        // epilogue-operand prefetch
        const float* Et = E + ((size_t)t * BB + b) * G3;
        float er = __ldcg(&Et[j]);
        float ei = __ldcg(&Et[HID + j]);
        float en = __ldcg(&Et[2 * HID + j]);
        float hp = __ldcg(&hprev[(size_t)b * HID + j]);

        // stage chunk0 (k 0..511) into hs0
#pragma unroll
        for (int i = 0; i < 16; i++) {
            int idx  = tid + i * 256;
            int hb   = idx >> 7;
            int koff = (idx & 127) * 4;
            float4 v = __ldcg((const float4*)&hprev[(size_t)hb * HID + koff]);
            *(float4*)&hs0[(size_t)hb * HPAD + koff] = v;
        }
        // issue chunk1 loads (k 512..1023) into registers (latency hides
        // under chunk-0 compute; STS to hs1 happens after compute0)
        float4 p[16];
#pragma unroll
        for (int i = 0; i < 16; i++) {
            int idx  = tid + i * 256;
            int hb   = idx >> 7;
            int koff = (idx & 127) * 4;
            p[i] = __ldcg((const float4*)&hprev[(size_t)hb * HID + KCH + koff]);
        }
        __syncthreads();

        unsigned long long aR0 = 0, aR1 = 0, aI0 = 0, aI1 = 0, aN0 = 0, aN1 = 0;

        // compute chunk0 (reads hs0)
#pragma unroll 8
        for (int kk = 0; kk < KCH; kk += 8) {
            U4 h0; h0.f4 = *(const float4*)&hrow0[kk];
            U4 h1; h1.f4 = *(const float4*)&hrow0[kk + 4];
            U4 r0; r0.f4 = *(const float4*)&Wr[kk];
            U4 r1; r1.f4 = *(const float4*)&Wr[kk + 4];
            U4 i0; i0.f4 = *(const float4*)&Wi[kk];
            U4 i1; i1.f4 = *(const float4*)&Wi[kk + 4];
            U4 n0; n0.f4 = *(const float4*)&Wn[kk];
            U4 n1; n1.f4 = *(const float4*)&Wn[kk + 4];
            fma2(aR0, h0.s.a, r0.s.a); fma2(aR0, h0.s.b, r0.s.b);
            fma2(aR1, h1.s.a, r1.s.a); fma2(aR1, h1.s.b, r1.s.b);
            fma2(aI0, h0.s.a, i0.s.a); fma2(aI0, h0.s.b, i0.s.b);
            fma2(aI1, h1.s.a, i1.s.a); fma2(aI1, h1.s.b, i1.s.b);
            fma2(aN0, h0.s.a, n0.s.a); fma2(aN0, h0.s.b, n0.s.b);
            fma2(aN1, h1.s.a, n1.s.a); fma2(aN1, h1.s.b, n1.s.b);
        }

        // commit chunk1 to hs1 (distinct buffer: no pre-sync needed)
#pragma unroll
        for (int i = 0; i < 16; i++) {
            int idx  = tid + i * 256;
            int hb   = idx >> 7;
            int koff = (idx & 127) * 4;
            *(float4*)&hs1[(size_t)hb * HPAD + koff] = p[i];
        }
        __syncthreads();

        // compute chunk1 (reads hs1, W offset +KCH)
#pragma unroll 8
        for (int kk = 0; kk < KCH; kk += 8) {
            U4 h0; h0.f4 = *(const float4*)&hrow1[kk];
            U4 h1; h1.f4 = *(const float4*)&hrow1[kk + 4];
            U4 r0; r0.f4 = *(const float4*)&Wr[KCH + kk];
            U4 r1; r1.f4 = *(const float4*)&Wr[KCH + kk + 4];
            U4 i0; i0.f4 = *(const float4*)&Wi[KCH + kk];
            U4 i1; i1.f4 = *(const float4*)&Wi[KCH + kk + 4];
            U4 n0; n0.f4 = *(const float4*)&Wn[KCH + kk];
            U4 n1; n1.f4 = *(const float4*)&Wn[KCH + kk + 4];
            fma2(aR0, h0.s.a, r0.s.a); fma2(aR0, h0.s.b, r0.s.b);
            fma2(aR1, h1.s.a, r1.s.a); fma2(aR1, h1.s.b, r1.s.b);
            fma2(aI0, h0.s.a, i0.s.a); fma2(aI0, h0.s.b, i0.s.b);
            fma2(aI1, h1.s.a, i1.s.a); fma2(aI1, h1.s.b, i1.s.b);
            fma2(aN0, h0.s.a, n0.s.a); fma2(aN0, h0.s.b, n0.s.b);
            fma2(aN1, h1.s.a, n1.s.a); fma2(aN1, h1.s.b, n1.s.b);
        }

        float gr = hadd2(aR0) + hadd2(aR1) + br;
        float gi = hadd2(aI0) + hadd2(aI1) + bi;
        float gn = hadd2(aN0) + hadd2(aN1) + bn;

        float r  = 1.f / (1.f + __expf(-(er + gr)));
        float ig = 1.f / (1.f + __expf(-(ei + gi)));
        float n  = tanhf(en + r * gn);
        Y[(size_t)t * BB * HID + (size_t)b * HID + j] = n + ig * (hp - n);

        if (t != T - 1) grid_barrier();
    }
}

// ------------------------- final hidden-state copy --------------------------
__global__ void copy_hidden(float* __restrict__ out) {
    int i = blockIdx.x * blockDim.x + threadIdx.x;
    if (i >= 3 * BB * HID) return;
    int l = i / (BB * HID);
    int r = i % (BB * HID);
    const float* src;
    if (l == 0)      src = g_Y0 + (size_t)(T0 - 1) * BB * HID;
    else if (l == 1) src = g_Y1 + (size_t)(T1 - 1) * BB * HID;
    else             src = g_Y2 + (size_t)(T2 - 1) * BB * HID;
    out[i] = src[r];
}

// ---------------------------------------------------------------------------
extern "C" void kernel_launch(void* const* d_in, const int* in_sizes, int n_in,
                              void* d_out, int out_size)
{
    const float* inputs = (const float*)d_in[0];
    const float* Wxh0 = (const float*)d_in[1];
    const float* bxh0 = (const float*)d_in[2];
    const float* Whh0 = (const float*)d_in[3];
    const float* bhh0 = (const float*)d_in[4];
    const float* Wnh0 = (const float*)d_in[5];
    const float* bnh0 = (const float*)d_in[6];
    const float* Wxh1 = (const float*)d_in[7];
    const float* bxh1 = (const float*)d_in[8];
    const float* Whh1 = (const float*)d_in[9];
    const float* bhh1 = (const float*)d_in[10];
    const float* Wnh1 = (const float*)d_in[11];
    const float* bnh1 = (const float*)d_in[12];
    const float* Wxh2 = (const float*)d_in[13];
    const float* bxh2 = (const float*)d_in[14];
    const float* Whh2 = (const float*)d_in[15];
    const float* bhh2 = (const float*)d_in[16];
    const float* Wnh2 = (const float*)d_in[17];
    const float* bnh2 = (const float*)d_in[18];
    const float* Wout = (const float*)d_in[19];
    const float* bout = (const float*)d_in[20];

    float *pX, *pM1, *pM2, *pE0, *pE1, *pE2, *pY0, *pY1, *pY2, *pBS, *pWS;
    cudaGetSymbolAddress((void**)&pX,  g_x);
    cudaGetSymbolAddress((void**)&pM1, g_ms1);
    cudaGetSymbolAddress((void**)&pM2, g_ms2);
    cudaGetSymbolAddress((void**)&pE0, g_E0);
    cudaGetSymbolAddress((void**)&pE1, g_E1);
    cudaGetSymbolAddress((void**)&pE2, g_E2);
    cudaGetSymbolAddress((void**)&pY0, g_Y0);
    cudaGetSymbolAddress((void**)&pY1, g_Y1);
    cudaGetSymbolAddress((void**)&pY2, g_Y2);
    cudaGetSymbolAddress((void**)&pBS, g_bs);
    cudaGetSymbolAddress((void**)&pWS, g_Wsum);

    static int smem_set = 0;
    const int LSMEM = (24 * WPAD + 64 * HPAD) * 4;   // 230,784 B
    if (!smem_set) {
        cudaFuncSetAttribute(layer_kernel,
                             cudaFuncAttributeMaxDynamicSharedMemorySize, LSMEM);
        smem_set = 1;
    }

    float* out = (float*)d_out;

    prep_kernel<<<(T0 * BB * DIN + 255) / 256, 256>>>(inputs);
    bias_wsum_kernel<<<(G3 * DIN + 255) / 256, 256>>>(bxh0, bnh0, bxh1, bnh1,
                                                      bxh2, bnh2, Wxh0, Wnh0);

    // ---- layer 0: fused E0 = x @ (Wxh0+Wnh0)^T + bias (ms0 == x) ----
    gemm_nt<<<dim3(G3 / GBN, (M0 + GBM - 1) / GBM), 256>>>(pE0, pX, pWS, pBS, M0, G3, DIN, 0);
    // ---- layer 1 ms-part (independent of Y0) ----
    gemm_nt<<<dim3(G3 / GBN, (M1 + GBM - 1) / GBM), 256>>>(pE1, pM1, Wnh1, pBS + G3, M1, G3, DIN, 0);

    layer_kernel<<<NBLK, 256, LSMEM>>>(pY0, pE0, Whh0, bhh0, T0);

    // ---- layer 1 xs-part (Y0 shifted by 1 step), accumulate ----
    gemm_nt<<<dim3(G3 / GBN, (M1 + GBM - 1) / GBM), 256>>>(pE1, pY0 + BB * HID, Wxh1, 0, M1, G3, HID, 1);
    layer_kernel<<<NBLK, 256, LSMEM>>>(pY1, pE1, Whh1, bhh1, T1);

    // ---- layer 2 ----
    gemm_nt<<<dim3(G3 / GBN, (M2 + GBM - 1) / GBM), 256>>>(pE2, pM2, Wnh2, pBS + 2 * G3, M2, G3, DIN, 0);
    gemm_nt<<<dim3(G3 / GBN, (M2 + GBM - 1) / GBM), 256>>>(pE2, pY1 + 2 * BB * HID, Wxh2, 0, M2, G3, HID, 1);
    layer_kernel<<<NBLK, 256, LSMEM>>>(pY2, pE2, Whh2, bhh2, T2);

    // ---- output projections + hidden states ----
    gemm_nt<<<dim3(DIN / GBN, (M0 + GBM - 1) / GBM), 256>>>(out,        pY0, Wout, bout, M0, DIN, HID, 0);
    gemm_nt<<<dim3(DIN / GBN, (M1 + GBM - 1) / GBM), 256>>>(out + OFF1, pY1, Wout, bout, M1, DIN, HID, 0);
    gemm_nt<<<dim3(DIN / GBN, (M2 + GBM - 1) / GBM), 256>>>(out + OFF2, pY2, Wout, bout, M2, DIN, HID, 0);
    copy_hidden<<<(3 * BB * HID + 255) / 256, 256>>>(out + OFFH);
}